// round 1
// baseline (speedup 1.0000x reference)
#include <cuda_runtime.h>

#define B_SZ 512
#define I_SZ 256
#define H_SZ 512

// Scratch (no allocs allowed) — transformed params + per-h constants + state ping-pong
__device__ float g_SG[H_SZ*H_SZ];
__device__ float g_MS[H_SZ*H_SZ];
__device__ float g_WE[H_SZ*H_SZ];
__device__ float g_WW[H_SZ*H_SZ];
__device__ float g_CN[H_SZ];
__device__ float g_CD[H_SZ];
__device__ float g_A [B_SZ*H_SZ];   // gleak*vleak + CN + w_num_sensory
__device__ float g_Dc[B_SZ*H_SZ];   // cm + gleak + CD + w_den_sensory
__device__ float g_v0[B_SZ*H_SZ];
__device__ float g_v1[B_SZ*H_SZ];

__device__ __forceinline__ float tanh_fast(float x){
    float y;
    asm("tanh.approx.f32 %0, %1;" : "=f"(y) : "f"(x));
    return y;
}

// Transform recurrent params once per launch.
// sigmoid((v-mu)*sigma) = 0.5*tanh(0.5*sigma*v - 0.5*sigma*mu) + 0.5
__global__ void k_prep(const float* __restrict__ mu, const float* __restrict__ sigma,
                       const float* __restrict__ W,  const float* __restrict__ erev){
    int idx = blockIdx.x*blockDim.x + threadIdx.x;
    if (idx < H_SZ*H_SZ){
        float s = sigma[idx], m = mu[idx], w = W[idx], e = erev[idx];
        g_SG[idx] = 0.5f*s;
        g_MS[idx] = -0.5f*s*m;
        g_WE[idx] = 0.5f*w*e;
        g_WW[idx] = 0.5f*w;
    }
}

// Per-h column sums of WE/WW (the "+0.5" constant part of the recurrent sigmoid)
__global__ void k_colsum(){
    int h = blockIdx.x;
    int t = threadIdx.x;
    float sn = 0.f, sd = 0.f;
    for (int i = t; i < H_SZ; i += 128){
        sn += g_WE[i*H_SZ + h];
        sd += g_WW[i*H_SZ + h];
    }
    __shared__ float rn[128], rd[128];
    rn[t] = sn; rd[t] = sd;
    __syncthreads();
    for (int s = 64; s > 0; s >>= 1){
        if (t < s){ rn[t] += rn[t+s]; rd[t] += rd[t+s]; }
        __syncthreads();
    }
    if (t == 0){ g_CN[h] = rn[0]; g_CD[h] = rd[0]; }
}

// Sensory currents (once): A[b,h], Dc[b,h], with all per-launch constants folded in.
__global__ __launch_bounds__(128) void k_sensory(
        const float* __restrict__ inp,
        const float* __restrict__ smu, const float* __restrict__ ssig,
        const float* __restrict__ sW,  const float* __restrict__ serev,
        const float* __restrict__ vleak, const float* __restrict__ gleak,
        const float* __restrict__ cm){
    __shared__ float u_s[32][33];
    __shared__ float sg_s[32][32];
    __shared__ float ms_s[32][32];
    __shared__ float we_s[32][32];
    __shared__ float ww_s[32][32];

    const int h0 = blockIdx.x * 32;
    const int b0 = blockIdx.y * 32;
    const int tx = threadIdx.x;
    const int hq = tx & 15;       // thread covers h = h0 + 2*hq + {0,1}
    const int bq = tx >> 4;       // thread covers b = b0 + 4*bq + {0..3}

    float num[4][2] = {};
    float den[4][2] = {};

    for (int i0 = 0; i0 < I_SZ; i0 += 32){
        __syncthreads();
        #pragma unroll
        for (int k = 0; k < 8; k++){
            int idx = tx + k*128;
            int bb = idx >> 5, ic = idx & 31;
            u_s[bb][ic] = inp[(b0+bb)*I_SZ + i0 + ic];
        }
        #pragma unroll
        for (int k = 0; k < 8; k++){
            int idx = tx + k*128;
            int ic = idx >> 5, hh = idx & 31;
            int g = (i0+ic)*H_SZ + h0 + hh;
            float s = ssig[g], m = smu[g], w = sW[g], e = serev[g];
            sg_s[ic][hh] = 0.5f*s;
            ms_s[ic][hh] = -0.5f*s*m;
            we_s[ic][hh] = w*e;
            ww_s[ic][hh] = w;
        }
        __syncthreads();
        #pragma unroll 8
        for (int ic = 0; ic < 32; ic++){
            float2 sg = *(const float2*)&sg_s[ic][2*hq];
            float2 ms = *(const float2*)&ms_s[ic][2*hq];
            float2 we = *(const float2*)&we_s[ic][2*hq];
            float2 ww = *(const float2*)&ww_s[ic][2*hq];
            #pragma unroll
            for (int j = 0; j < 4; j++){
                float u = u_s[4*bq + j][ic];
                float t0 = tanh_fast(fmaf(u, sg.x, ms.x));
                float t1 = tanh_fast(fmaf(u, sg.y, ms.y));
                float a0 = fmaf(t0, 0.5f, 0.5f);
                float a1 = fmaf(t1, 0.5f, 0.5f);
                num[j][0] = fmaf(we.x, a0, num[j][0]);
                den[j][0] = fmaf(ww.x, a0, den[j][0]);
                num[j][1] = fmaf(we.y, a1, num[j][1]);
                den[j][1] = fmaf(ww.y, a1, den[j][1]);
            }
        }
    }

    #pragma unroll
    for (int k = 0; k < 2; k++){
        int h = h0 + 2*hq + k;
        float base_n = gleak[h]*vleak[h] + g_CN[h];
        float base_d = cm[h] + gleak[h] + g_CD[h];
        #pragma unroll
        for (int j = 0; j < 4; j++){
            int b = b0 + 4*bq + j;
            g_A [b*H_SZ + h] = num[j][k] + base_n;
            g_Dc[b*H_SZ + h] = den[j][k] + base_d;
        }
    }
}

// One recurrent unfold: vout = (cm*vin + A + sum_i WE*tanh) / (Dc + sum_i WW*tanh + 1e-8)
__global__ __launch_bounds__(128) void k_step(const float* vext, float* voutext,
                                              int sel_in, int sel_out,
                                              const float* __restrict__ cm){
    const float* vin  = (sel_in  == 0) ? g_v0 : ((sel_in  == 1) ? g_v1 : vext);
    float*       vout = (sel_out == 0) ? g_v0 : ((sel_out == 1) ? g_v1 : voutext);

    __shared__ float v_s[32][33];
    __shared__ float sg_s[32][32];
    __shared__ float ms_s[32][32];
    __shared__ float we_s[32][32];
    __shared__ float ww_s[32][32];

    const int h0 = blockIdx.x * 32;
    const int b0 = blockIdx.y * 32;
    const int tx = threadIdx.x;
    const int hq = tx & 15;
    const int bq = tx >> 4;

    float num[4][2] = {};
    float den[4][2] = {};

    for (int i0 = 0; i0 < H_SZ; i0 += 32){
        __syncthreads();
        #pragma unroll
        for (int k = 0; k < 8; k++){
            int idx = tx + k*128;
            int bb = idx >> 5, ic = idx & 31;
            v_s[bb][ic] = vin[(b0+bb)*H_SZ + i0 + ic];
        }
        #pragma unroll
        for (int k = 0; k < 8; k++){
            int idx = tx + k*128;
            int ic = idx >> 5, hh = idx & 31;
            int g = (i0+ic)*H_SZ + h0 + hh;
            sg_s[ic][hh] = g_SG[g];
            ms_s[ic][hh] = g_MS[g];
            we_s[ic][hh] = g_WE[g];
            ww_s[ic][hh] = g_WW[g];
        }
        __syncthreads();
        #pragma unroll 8
        for (int ic = 0; ic < 32; ic++){
            float2 sg = *(const float2*)&sg_s[ic][2*hq];
            float2 ms = *(const float2*)&ms_s[ic][2*hq];
            float2 we = *(const float2*)&we_s[ic][2*hq];
            float2 ww = *(const float2*)&ww_s[ic][2*hq];
            #pragma unroll
            for (int j = 0; j < 4; j++){
                float v = v_s[4*bq + j][ic];
                float t0 = tanh_fast(fmaf(v, sg.x, ms.x));
                float t1 = tanh_fast(fmaf(v, sg.y, ms.y));
                num[j][0] = fmaf(we.x, t0, num[j][0]);
                den[j][0] = fmaf(ww.x, t0, den[j][0]);
                num[j][1] = fmaf(we.y, t1, num[j][1]);
                den[j][1] = fmaf(ww.y, t1, den[j][1]);
            }
        }
    }

    #pragma unroll
    for (int k = 0; k < 2; k++){
        int h = h0 + 2*hq + k;
        float cmh = cm[h];
        #pragma unroll
        for (int j = 0; j < 4; j++){
            int b = b0 + 4*bq + j;
            float n = fmaf(cmh, vin[b*H_SZ + h], g_A[b*H_SZ + h]) + num[j][k];
            float d = g_Dc[b*H_SZ + h] + den[j][k];
            vout[b*H_SZ + h] = __fdividef(n, d + 1e-8f);
        }
    }
}

extern "C" void kernel_launch(void* const* d_in, const int* in_sizes, int n_in,
                              void* d_out, int out_size){
    const float* inputs = (const float*)d_in[0];
    const float* state  = (const float*)d_in[1];
    const float* smu    = (const float*)d_in[2];
    const float* ssig   = (const float*)d_in[3];
    const float* sW     = (const float*)d_in[4];
    const float* serev  = (const float*)d_in[5];
    const float* mu     = (const float*)d_in[6];
    const float* sigma  = (const float*)d_in[7];
    const float* W      = (const float*)d_in[8];
    const float* erev   = (const float*)d_in[9];
    const float* vleak  = (const float*)d_in[10];
    const float* gleak  = (const float*)d_in[11];
    const float* cm     = (const float*)d_in[12];
    float* out = (float*)d_out;

    k_prep<<<(H_SZ*H_SZ + 255)/256, 256>>>(mu, sigma, W, erev);
    k_colsum<<<H_SZ, 128>>>();

    dim3 grid(H_SZ/32, B_SZ/32);   // (16, 16)
    k_sensory<<<grid, 128>>>(inputs, smu, ssig, sW, serev, vleak, gleak, cm);

    // 6 unfolds: state -> v0 -> v1 -> v0 -> v1 -> v0 -> out
    k_step<<<grid, 128>>>(state,   nullptr, 2, 0, cm);
    k_step<<<grid, 128>>>(nullptr, nullptr, 0, 1, cm);
    k_step<<<grid, 128>>>(nullptr, nullptr, 1, 0, cm);
    k_step<<<grid, 128>>>(nullptr, nullptr, 0, 1, cm);
    k_step<<<grid, 128>>>(nullptr, nullptr, 1, 0, cm);
    k_step<<<grid, 128>>>(nullptr, out,     0, 2, cm);
}